// round 2
// baseline (speedup 1.0000x reference)
#include <cuda_runtime.h>
#include <cuda_bf16.h>

// PEPS 6x6, D=4, phys=2, batch=1024. Row-sweep exact contraction, snake order.
// One CTA (1024 threads) per configuration. float4-vectorized interior steps.

#define NT 1024

__device__ __forceinline__ void step_generic(
    const float* __restrict__ Win, float* __restrict__ Wout,
    const float* __restrict__ A, int F, int K, int N,
    int Pu, int ud, int Srin, int tid)
{
    int total = N * F;
    for (int o = tid; o < total; o += NT) {
        int n = o / F;
        int m = o - n * F;
        int dp = m / Pu;
        int ur = m - dp * Pu;
        int inb = dp * ud * Pu + ur;
        float s = 0.f;
        for (int k = 0; k < K; ++k) {
            int rin = k / ud;
            int u = k - rin * ud;
            s = fmaf(Win[inb + rin * Srin + u * Pu], A[k * N + n], s);
        }
        Wout[n * F + m] = s;
    }
}

// Interior rows, steps 0..4: F=1024, N=16, Pu = 1<<PSH >= 4.
// Thread -> (g = tid>>8 picks 4 n's, t = tid&255 picks m-vec 4t..4t+3).
// Per k: one LDS.128 of input + one broadcast LDS.128 of A row slice,
// 16 FFMA. All stores are STS.128.
template <int K, int PSH>
__device__ __forceinline__ void step_fast_vec(
    const float* __restrict__ Win, float* __restrict__ Wout,
    const float* __restrict__ A, int tid)
{
    const int g = tid >> 8;           // n-group: n = 4g..4g+3
    const int t = tid & 255;
    const int mb = t << 2;            // m-vec base (4-aligned, stays in Pu block)
    const int dp = mb >> PSH;
    const int ur = mb & ((1 << PSH) - 1);
    const int inb = (dp << (PSH + 2)) + ur;

    float4 acc[4];
#pragma unroll
    for (int n = 0; n < 4; ++n) acc[n] = make_float4(0.f, 0.f, 0.f, 0.f);

#pragma unroll
    for (int k = 0; k < K; ++k) {
        const int off = (k >> 2) * 4096 + ((k & 3) << PSH);
        const float4 xv = *(const float4*)(Win + inb + off);
        const float4 a4 = *(const float4*)(A + k * 16 + g * 4);
#pragma unroll
        for (int n = 0; n < 4; ++n) {
            const float a = (n == 0) ? a4.x : (n == 1) ? a4.y : (n == 2) ? a4.z : a4.w;
            acc[n].x = fmaf(xv.x, a, acc[n].x);
            acc[n].y = fmaf(xv.y, a, acc[n].y);
            acc[n].z = fmaf(xv.z, a, acc[n].z);
            acc[n].w = fmaf(xv.w, a, acc[n].w);
        }
    }

#pragma unroll
    for (int n = 0; n < 4; ++n)
        *(float4*)(Wout + (g * 4 + n) * 1024 + mb) = acc[n];
}

// Interior rows, step 5: F=1024, N=4, K=16, Pu=1 (PSH=0).
// One thread per m; vectorize the input load over the u-axis instead.
__device__ __forceinline__ void step_fast_last(
    const float* __restrict__ Win, float* __restrict__ Wout,
    const float* __restrict__ A, int tid)
{
    const int m = tid;                // 1024 threads = F
    float acc[4] = {0.f, 0.f, 0.f, 0.f};

#pragma unroll
    for (int rin = 0; rin < 4; ++rin) {
        const float4 xv = *(const float4*)(Win + m * 4 + rin * 4096);  // over u
#pragma unroll
        for (int u = 0; u < 4; ++u) {
            const float xs = (u == 0) ? xv.x : (u == 1) ? xv.y : (u == 2) ? xv.z : xv.w;
            const float4 a4 = *(const float4*)(A + (rin * 4 + u) * 4); // over n
            acc[0] = fmaf(xs, a4.x, acc[0]);
            acc[1] = fmaf(xs, a4.y, acc[1]);
            acc[2] = fmaf(xs, a4.z, acc[2]);
            acc[3] = fmaf(xs, a4.w, acc[3]);
        }
    }
#pragma unroll
    for (int n = 0; n < 4; ++n) Wout[n * 1024 + m] = acc[n];
}

__global__ __launch_bounds__(NT, 1)
void peps_amp_kernel(const int* __restrict__ x, const float* __restrict__ T,
                     float* __restrict__ out)
{
    extern __shared__ float smem[];
    float* W0 = smem;                            // 16384
    float* W1 = smem + 16384;                    // 16384
    float* As = smem + 32768;                    // 6 * 256
    int* spins = (int*)(smem + 32768 + 1536);    // 36

    const int b = blockIdx.x;
    const int tid = threadIdx.x;

    if (tid < 36) spins[tid] = x[b * 36 + tid];
    if (tid == 0) W0[0] = 1.0f;
    __syncthreads();

    float* bufs[2] = { W0, W1 };
    int cur = 0;

    for (int i = 0; i < 6; ++i) {
        const int ud = (i == 0) ? 1 : 4;
        const int dd = (i == 5) ? 1 : 4;
        const bool l2r = ((i & 1) == 0);

        // Stage this row's 6 site matrices: As[st][k*N + n],
        // k = rin*ud + u, n = rout*dd + d.
        for (int st = 0; st < 6; ++st) {
            const int Rin  = (st == 0) ? 1 : 4;
            const int Rout = (st == 5) ? 1 : 4;
            const int K = ud * Rin;
            const int N = Rout * dd;
            const int jc = l2r ? st : (5 - st);
            const int s = spins[i * 6 + jc];
            const float* Tb = T + (size_t)((i * 6 + jc) * 2 + s) * 256;
            for (int idx = tid; idx < K * N; idx += NT) {
                int k = idx / N, n = idx - k * N;
                int rin = k / ud, u = k - rin * ud;
                int rout = n / dd, d = n - rout * dd;
                int r = l2r ? rout : rin;
                int l = l2r ? rin : rout;
                As[st * 256 + idx] = Tb[u * 64 + r * 16 + d * 4 + l];
            }
        }
        __syncthreads();

        for (int st = 0; st < 6; ++st) {
            const float* Win = bufs[cur];
            float* Wout = bufs[cur ^ 1];
            const float* A = As + st * 256;

            if (ud == 4 && dd == 4) {
                switch (st) {
                    case 0: step_fast_vec<4, 10>(Win, Wout, A, tid); break;
                    case 1: step_fast_vec<16, 8>(Win, Wout, A, tid); break;
                    case 2: step_fast_vec<16, 6>(Win, Wout, A, tid); break;
                    case 3: step_fast_vec<16, 4>(Win, Wout, A, tid); break;
                    case 4: step_fast_vec<16, 2>(Win, Wout, A, tid); break;
                    default: step_fast_last(Win, Wout, A, tid); break;
                }
            } else {
                const int Rin  = (st == 0) ? 1 : 4;
                const int Rout = (st == 5) ? 1 : 4;
                const int K = ud * Rin;
                const int N = Rout * dd;
                const int Pd = (dd == 1) ? 1 : (1 << (2 * st));
                const int Pu = (ud == 1) ? 1 : (1 << (2 * (5 - st)));
                step_generic(Win, Wout, A, Pd * Pu, K, N, Pu, ud,
                             Pd * ud * Pu, tid);
            }
            cur ^= 1;
            __syncthreads();
        }
    }

    if (tid == 0) out[b] = bufs[cur][0];
}

extern "C" void kernel_launch(void* const* d_in, const int* in_sizes, int n_in,
                              void* d_out, int out_size)
{
    const int T_ELEMS = 6 * 6 * 2 * 4 * 4 * 4 * 4;   // 73728
    const int* x;
    const float* T;
    if (in_sizes[0] == T_ELEMS) {
        T = (const float*)d_in[0];
        x = (const int*)d_in[1];
    } else {
        x = (const int*)d_in[0];
        T = (const float*)d_in[1];
    }

    const int smem_bytes = (16384 + 16384 + 6 * 256 + 64) * (int)sizeof(float);
    cudaFuncSetAttribute(peps_amp_kernel,
                         cudaFuncAttributeMaxDynamicSharedMemorySize, smem_bytes);

    peps_amp_kernel<<<out_size, NT, smem_bytes>>>(x, T, (float*)d_out);
}

// round 3
// speedup vs baseline: 1.4710x; 1.4710x over previous
#include <cuda_runtime.h>
#include <cuda_bf16.h>

// PEPS 6x6, D=4, phys=2, batch=1024. Row-sweep exact contraction, snake order.
// One CTA (512 threads) per configuration, SINGLE W buffer (compute-in-regs,
// barrier, write-back), 2 CTAs/SM. Interior steps: 4m x 8n register blocking.

#define NT 512

// Generic step, two-phase (read->acc, BAR, write). N*F <= 4096 -> <=8 outs/thread.
__device__ __forceinline__ void step_generic(
    float* __restrict__ W, const float* __restrict__ A,
    int F, int K, int N, int Pu, int ud, int Srin, int tid)
{
    const int total = N * F;
    float accl[8];
    int cnt = 0;
    for (int o = tid; o < total; o += NT) {
        int n = o / F;
        int m = o - n * F;
        int dp = m / Pu;
        int ur = m - dp * Pu;
        int inb = dp * ud * Pu + ur;
        float s = 0.f;
        for (int k = 0; k < K; ++k) {
            int rin = k / ud;
            int u = k - rin * ud;
            s = fmaf(W[inb + rin * Srin + u * Pu], A[k * N + n], s);
        }
        accl[cnt++] = s;
    }
    __syncthreads();
    cnt = 0;
    for (int o = tid; o < total; o += NT) {
        int n = o / F;
        int m = o - n * F;
        W[n * F + m] = accl[cnt++];
    }
    __syncthreads();
}

// Interior rows, steps 0..4: F=1024, N=16, Pu = 1<<PSH >= 4.
// 512 threads: g = tid>>8 picks 8 n's, t = tid&255 picks m-vec 4t..4t+3.
// Per k: 1 LDS.128 input + 2 broadcast LDS.128 A, 32 FFMA  -> 1.5 B/FMA.
template <int K, int PSH>
__device__ __forceinline__ void step_fast_vec(
    float* __restrict__ W, const float* __restrict__ A, int tid)
{
    const int g = tid >> 8;           // n-group: n = 8g..8g+7
    const int t = tid & 255;
    const int mb = t << 2;            // m-vec base (4-aligned within Pu block)
    const int dp = mb >> PSH;
    const int ur = mb & ((1 << PSH) - 1);
    const int inb = (dp << (PSH + 2)) + ur;

    float4 acc[8];
#pragma unroll
    for (int n = 0; n < 8; ++n) acc[n] = make_float4(0.f, 0.f, 0.f, 0.f);

#pragma unroll
    for (int k = 0; k < K; ++k) {
        const int off = (k >> 2) * 4096 + ((k & 3) << PSH);
        const float4 xv = *(const float4*)(W + inb + off);
        const float4 alo = *(const float4*)(A + k * 16 + g * 8);
        const float4 ahi = *(const float4*)(A + k * 16 + g * 8 + 4);
#pragma unroll
        for (int n = 0; n < 8; ++n) {
            const float a = (n == 0) ? alo.x : (n == 1) ? alo.y :
                            (n == 2) ? alo.z : (n == 3) ? alo.w :
                            (n == 4) ? ahi.x : (n == 5) ? ahi.y :
                            (n == 6) ? ahi.z : ahi.w;
            acc[n].x = fmaf(xv.x, a, acc[n].x);
            acc[n].y = fmaf(xv.y, a, acc[n].y);
            acc[n].z = fmaf(xv.z, a, acc[n].z);
            acc[n].w = fmaf(xv.w, a, acc[n].w);
        }
    }

    __syncthreads();
#pragma unroll
    for (int n = 0; n < 8; ++n)
        *(float4*)(W + (g * 8 + n) * 1024 + mb) = acc[n];
    __syncthreads();
}

// Interior rows, step 5: F=1024, N=4, K=16 (layout rin*4096 + m*4 + u).
// 512 threads, 2 m each: 8 outputs/thread.
__device__ __forceinline__ void step_fast_last(
    float* __restrict__ W, const float* __restrict__ A, int tid)
{
    const int m0 = tid * 2;
    float acc[2][4];
#pragma unroll
    for (int p = 0; p < 2; ++p)
#pragma unroll
        for (int n = 0; n < 4; ++n) acc[p][n] = 0.f;

#pragma unroll
    for (int rin = 0; rin < 4; ++rin) {
        const float4 xv0 = *(const float4*)(W + m0 * 4 + rin * 4096);
        const float4 xv1 = *(const float4*)(W + (m0 + 1) * 4 + rin * 4096);
#pragma unroll
        for (int u = 0; u < 4; ++u) {
            const float x0 = (u == 0) ? xv0.x : (u == 1) ? xv0.y : (u == 2) ? xv0.z : xv0.w;
            const float x1 = (u == 0) ? xv1.x : (u == 1) ? xv1.y : (u == 2) ? xv1.z : xv1.w;
            const float4 a4 = *(const float4*)(A + (rin * 4 + u) * 4);
            acc[0][0] = fmaf(x0, a4.x, acc[0][0]);
            acc[0][1] = fmaf(x0, a4.y, acc[0][1]);
            acc[0][2] = fmaf(x0, a4.z, acc[0][2]);
            acc[0][3] = fmaf(x0, a4.w, acc[0][3]);
            acc[1][0] = fmaf(x1, a4.x, acc[1][0]);
            acc[1][1] = fmaf(x1, a4.y, acc[1][1]);
            acc[1][2] = fmaf(x1, a4.z, acc[1][2]);
            acc[1][3] = fmaf(x1, a4.w, acc[1][3]);
        }
    }
    __syncthreads();
#pragma unroll
    for (int n = 0; n < 4; ++n) {
        W[n * 1024 + m0] = acc[0][n];
        W[n * 1024 + m0 + 1] = acc[1][n];
    }
    __syncthreads();
}

__global__ __launch_bounds__(NT, 2)
void peps_amp_kernel(const int* __restrict__ x, const float* __restrict__ T,
                     float* __restrict__ out)
{
    extern __shared__ float smem[];
    float* W = smem;                             // 16384
    float* As = smem + 16384;                    // 6 * 256
    int* spins = (int*)(smem + 16384 + 1536);    // 36 (+ pad)

    const int b = blockIdx.x;
    const int tid = threadIdx.x;

    if (tid < 36) spins[tid] = x[b * 36 + tid];
    if (tid == 0) W[0] = 1.0f;
    __syncthreads();

    for (int i = 0; i < 6; ++i) {
        const int ud = (i == 0) ? 1 : 4;
        const int dd = (i == 5) ? 1 : 4;
        const bool l2r = ((i & 1) == 0);

        // Stage this row's 6 site matrices: As[st][k*N + n],
        // k = rin*ud + u, n = rout*dd + d.
        for (int st = 0; st < 6; ++st) {
            const int Rin  = (st == 0) ? 1 : 4;
            const int Rout = (st == 5) ? 1 : 4;
            const int K = ud * Rin;
            const int N = Rout * dd;
            const int jc = l2r ? st : (5 - st);
            const int s = spins[i * 6 + jc];
            const float* Tb = T + (size_t)((i * 6 + jc) * 2 + s) * 256;
            for (int idx = tid; idx < K * N; idx += NT) {
                int k = idx / N, n = idx - k * N;
                int rin = k / ud, u = k - rin * ud;
                int rout = n / dd, d = n - rout * dd;
                int r = l2r ? rout : rin;
                int l = l2r ? rin : rout;
                As[st * 256 + idx] = Tb[u * 64 + r * 16 + d * 4 + l];
            }
        }
        __syncthreads();

        for (int st = 0; st < 6; ++st) {
            const float* A = As + st * 256;

            if (ud == 4 && dd == 4) {
                switch (st) {
                    case 0: step_fast_vec<4, 10>(W, A, tid); break;
                    case 1: step_fast_vec<16, 8>(W, A, tid); break;
                    case 2: step_fast_vec<16, 6>(W, A, tid); break;
                    case 3: step_fast_vec<16, 4>(W, A, tid); break;
                    case 4: step_fast_vec<16, 2>(W, A, tid); break;
                    default: step_fast_last(W, A, tid); break;
                }
            } else {
                const int Rin  = (st == 0) ? 1 : 4;
                const int Rout = (st == 5) ? 1 : 4;
                const int K = ud * Rin;
                const int N = Rout * dd;
                const int Pd = (dd == 1) ? 1 : (1 << (2 * st));
                const int Pu = (ud == 1) ? 1 : (1 << (2 * (5 - st)));
                step_generic(W, A, Pd * Pu, K, N, Pu, ud,
                             Pd * ud * Pu, tid);
            }
        }
    }

    if (tid == 0) out[b] = W[0];
}

extern "C" void kernel_launch(void* const* d_in, const int* in_sizes, int n_in,
                              void* d_out, int out_size)
{
    const int T_ELEMS = 6 * 6 * 2 * 4 * 4 * 4 * 4;   // 73728
    const int* x;
    const float* T;
    if (in_sizes[0] == T_ELEMS) {
        T = (const float*)d_in[0];
        x = (const int*)d_in[1];
    } else {
        x = (const int*)d_in[0];
        T = (const float*)d_in[1];
    }

    const int smem_bytes = (16384 + 1536 + 64) * (int)sizeof(float);
    cudaFuncSetAttribute(peps_amp_kernel,
                         cudaFuncAttributeMaxDynamicSharedMemorySize, smem_bytes);

    peps_amp_kernel<<<out_size, NT, smem_bytes>>>(x, T, (float*)d_out);
}

// round 4
// speedup vs baseline: 1.5798x; 1.0740x over previous
#include <cuda_runtime.h>
#include <cuda_bf16.h>

// PEPS 6x6, D=4, phys=2, batch=1024. Row-sweep exact contraction, snake order.
// One CTA (512 threads) per configuration, single W buffer, 2 CTAs/SM.
// Interior steps use packed fma.rn.f32x2 (2 fp32 MACs / FMA-pipe inst).

#define NT 512

typedef unsigned long long u64;

__device__ __forceinline__ u64 pk(float v) {
    u64 r;
    asm("mov.b64 %0, {%1, %1};" : "=l"(r) : "f"(v));
    return r;
}
__device__ __forceinline__ void fma2(u64& d, u64 a, u64 b) {
    asm("fma.rn.f32x2 %0, %1, %2, %0;" : "+l"(d) : "l"(a), "l"(b));
}
__device__ __forceinline__ float2 upk(u64 v) {
    float2 r;
    asm("mov.b64 {%0, %1}, %2;" : "=f"(r.x), "=f"(r.y) : "l"(v));
    return r;
}

// Generic step (boundary rows), two-phase over the single buffer.
__device__ __forceinline__ void step_generic(
    float* __restrict__ W, const float* __restrict__ A,
    int F, int K, int N, int Pu, int ud, int Srin, int tid)
{
    const int total = N * F;
    float accl[8];
    int cnt = 0;
    for (int o = tid; o < total; o += NT) {
        int n = o / F;
        int m = o - n * F;
        int dp = m / Pu;
        int ur = m - dp * Pu;
        int inb = dp * ud * Pu + ur;
        float s = 0.f;
        for (int k = 0; k < K; ++k) {
            int rin = k / ud;
            int u = k - rin * ud;
            s = fmaf(W[inb + rin * Srin + u * Pu], A[k * N + n], s);
        }
        accl[cnt++] = s;
    }
    __syncthreads();
    cnt = 0;
    for (int o = tid; o < total; o += NT) {
        int n = o / F;
        int m = o - n * F;
        W[n * F + m] = accl[cnt++];
    }
    __syncthreads();
}

// Interior rows, steps 0..4: F=1024, N=16, Pu = 1<<PSH >= 4.
// g = tid>>8 picks 8 n's, t = tid&255 picks m-vec 4t..4t+3 (2 f32x2 packs).
// Per k: 1 LDS.128 input + 2 broadcast LDS.128 A + 8 dup-movs + 16 FFMA2.
template <int K, int PSH>
__device__ __forceinline__ void step_fast_vec(
    float* __restrict__ W, const float* __restrict__ A, int tid)
{
    const int g = tid >> 8;           // n-group: n = 8g..8g+7
    const int t = tid & 255;
    const int mb = t << 2;            // m-vec base
    const int dp = mb >> PSH;
    const int ur = mb & ((1 << PSH) - 1);
    const int inb = (dp << (PSH + 2)) + ur;

    u64 acc[8][2];
#pragma unroll
    for (int n = 0; n < 8; ++n) { acc[n][0] = 0ull; acc[n][1] = 0ull; }

#pragma unroll
    for (int k = 0; k < K; ++k) {
        const int off = (k >> 2) * 4096 + ((k & 3) << PSH);
        const ulonglong2 xv = *(const ulonglong2*)(W + inb + off);
        const float4 alo = *(const float4*)(A + k * 16 + g * 8);
        const float4 ahi = *(const float4*)(A + k * 16 + g * 8 + 4);
        const float av[8] = { alo.x, alo.y, alo.z, alo.w,
                              ahi.x, ahi.y, ahi.z, ahi.w };
#pragma unroll
        for (int n = 0; n < 8; ++n) {
            const u64 a2 = pk(av[n]);
            fma2(acc[n][0], xv.x, a2);
            fma2(acc[n][1], xv.y, a2);
        }
    }

    __syncthreads();
#pragma unroll
    for (int n = 0; n < 8; ++n) {
        ulonglong2 o;
        o.x = acc[n][0];
        o.y = acc[n][1];
        *(ulonglong2*)(W + (g * 8 + n) * 1024 + mb) = o;
    }
    __syncthreads();
}

// Interior rows, step 5: F=1024, N=4, K=16 (input layout rin*4096 + m*4 + u).
// 512 threads, 2 m each; acc packed over n-pairs.
__device__ __forceinline__ void step_fast_last(
    float* __restrict__ W, const float* __restrict__ A, int tid)
{
    const int m0 = tid * 2;
    u64 acc[2][2];                    // [m-slot][n-pair]
    acc[0][0] = acc[0][1] = acc[1][0] = acc[1][1] = 0ull;

#pragma unroll
    for (int rin = 0; rin < 4; ++rin) {
        const float4 xv0 = *(const float4*)(W + m0 * 4 + rin * 4096);
        const float4 xv1 = *(const float4*)(W + (m0 + 1) * 4 + rin * 4096);
#pragma unroll
        for (int u = 0; u < 4; ++u) {
            const float x0 = (u == 0) ? xv0.x : (u == 1) ? xv0.y : (u == 2) ? xv0.z : xv0.w;
            const float x1 = (u == 0) ? xv1.x : (u == 1) ? xv1.y : (u == 2) ? xv1.z : xv1.w;
            const ulonglong2 a2 = *(const ulonglong2*)(A + (rin * 4 + u) * 4);
            const u64 p0 = pk(x0);
            const u64 p1 = pk(x1);
            fma2(acc[0][0], p0, a2.x);
            fma2(acc[0][1], p0, a2.y);
            fma2(acc[1][0], p1, a2.x);
            fma2(acc[1][1], p1, a2.y);
        }
    }
    __syncthreads();
#pragma unroll
    for (int p = 0; p < 2; ++p) {
        const float2 v01 = upk(acc[p][0]);
        const float2 v23 = upk(acc[p][1]);
        W[0 * 1024 + m0 + p] = v01.x;
        W[1 * 1024 + m0 + p] = v01.y;
        W[2 * 1024 + m0 + p] = v23.x;
        W[3 * 1024 + m0 + p] = v23.y;
    }
    __syncthreads();
}

__global__ __launch_bounds__(NT, 2)
void peps_amp_kernel(const int* __restrict__ x, const float* __restrict__ T,
                     float* __restrict__ out)
{
    extern __shared__ float smem[];
    float* W = smem;                             // 16384
    float* As = smem + 16384;                    // 6 * 256
    int* spins = (int*)(smem + 16384 + 1536);    // 36 (+ pad)

    const int b = blockIdx.x;
    const int tid = threadIdx.x;

    if (tid < 36) spins[tid] = x[b * 36 + tid];
    if (tid == 0) W[0] = 1.0f;
    __syncthreads();

    for (int i = 0; i < 6; ++i) {
        const int ud = (i == 0) ? 1 : 4;
        const int dd = (i == 5) ? 1 : 4;
        const bool l2r = ((i & 1) == 0);

        // Stage this row's 6 site matrices: As[st][k*N + n],
        // k = rin*ud + u, n = rout*dd + d.
        for (int st = 0; st < 6; ++st) {
            const int Rin  = (st == 0) ? 1 : 4;
            const int Rout = (st == 5) ? 1 : 4;
            const int K = ud * Rin;
            const int N = Rout * dd;
            const int jc = l2r ? st : (5 - st);
            const int s = spins[i * 6 + jc];
            const float* Tb = T + (size_t)((i * 6 + jc) * 2 + s) * 256;
            for (int idx = tid; idx < K * N; idx += NT) {
                int k = idx / N, n = idx - k * N;
                int rin = k / ud, u = k - rin * ud;
                int rout = n / dd, d = n - rout * dd;
                int r = l2r ? rout : rin;
                int l = l2r ? rin : rout;
                As[st * 256 + idx] = Tb[u * 64 + r * 16 + d * 4 + l];
            }
        }
        __syncthreads();

        for (int st = 0; st < 6; ++st) {
            const float* A = As + st * 256;

            if (ud == 4 && dd == 4) {
                switch (st) {
                    case 0: step_fast_vec<4, 10>(W, A, tid); break;
                    case 1: step_fast_vec<16, 8>(W, A, tid); break;
                    case 2: step_fast_vec<16, 6>(W, A, tid); break;
                    case 3: step_fast_vec<16, 4>(W, A, tid); break;
                    case 4: step_fast_vec<16, 2>(W, A, tid); break;
                    default: step_fast_last(W, A, tid); break;
                }
            } else {
                const int Rin  = (st == 0) ? 1 : 4;
                const int Rout = (st == 5) ? 1 : 4;
                const int K = ud * Rin;
                const int N = Rout * dd;
                const int Pd = (dd == 1) ? 1 : (1 << (2 * st));
                const int Pu = (ud == 1) ? 1 : (1 << (2 * (5 - st)));
                step_generic(W, A, Pd * Pu, K, N, Pu, ud,
                             Pd * ud * Pu, tid);
            }
        }
    }

    if (tid == 0) out[b] = W[0];
}

extern "C" void kernel_launch(void* const* d_in, const int* in_sizes, int n_in,
                              void* d_out, int out_size)
{
    const int T_ELEMS = 6 * 6 * 2 * 4 * 4 * 4 * 4;   // 73728
    const int* x;
    const float* T;
    if (in_sizes[0] == T_ELEMS) {
        T = (const float*)d_in[0];
        x = (const int*)d_in[1];
    } else {
        x = (const int*)d_in[0];
        T = (const float*)d_in[1];
    }

    const int smem_bytes = (16384 + 1536 + 64) * (int)sizeof(float);
    cudaFuncSetAttribute(peps_amp_kernel,
                         cudaFuncAttributeMaxDynamicSharedMemorySize, smem_bytes);

    peps_amp_kernel<<<out_size, NT, smem_bytes>>>(x, T, (float*)d_out);
}